// round 7
// baseline (speedup 1.0000x reference)
#include <cuda_runtime.h>

#define G3 (64 * 64 * 64)          // 262144 voxels per batch
#define PAIRS_PER_B (G3 / 2)       // 131072 voxel pairs per batch

typedef unsigned long long u64;

__device__ __forceinline__ u64 f2fma(u64 a, u64 b, u64 c) {
    u64 d; asm("fma.rn.f32x2 %0, %1, %2, %3;" : "=l"(d) : "l"(a), "l"(b), "l"(c)); return d;
}
__device__ __forceinline__ u64 f2mul(u64 a, u64 b) {
    u64 d; asm("mul.rn.f32x2 %0, %1, %2;" : "=l"(d) : "l"(a), "l"(b)); return d;
}
__device__ __forceinline__ u64 f2dup(float x) {
    u64 d; asm("mov.b64 %0, {%1, %1};" : "=l"(d) : "f"(x)); return d;
}

// One thread = one voxel PAIR (v, v+1) x ONE output index i (= blockIdx.y).
// Live state: T2 (27 u64 = 54 regs) + A (9 u64 = 18) + temps -> ~110 actual.
// launch_bounds(128,4): 128-reg cap, 4 CTAs/SM = 16 warps.
__global__ void __launch_bounds__(128, 4)
alphaC0_kernel(const float* __restrict__ alpha,
               const float* __restrict__ C0,
               float* __restrict__ out,
               int pairs_total)
{
    __shared__ u64 c0s2[81];       // C0 duplicated into both f32x2 lanes
    if (threadIdx.x < 81) c0s2[threadIdx.x] = f2dup(C0[threadIdx.x]);
    __syncthreads();

    const int tid = blockIdx.x * blockDim.x + threadIdx.x;
    if (tid >= pairs_total) return;

    const int i = blockIdx.y;                    // output index slice (0..2), uniform
    const int b = tid >> 17;                     // / PAIRS_PER_B
    const int v = (tid & (PAIRS_PER_B - 1)) * 2;

    // A2[m][c] = packed { A(v)[m][c], A(v+1)[m][c] }
    u64 A2[3][3];
#pragma unroll
    for (int m = 0; m < 3; m++)
#pragma unroll
        for (int c = 0; c < 3; c++)
            A2[m][c] = *reinterpret_cast<const u64*>(
                &alpha[(size_t)((b * 3 + m) * 3 + c) * G3 + v]);

    // a_m = A2[m][i] via uniform branch
    u64 a0, a1, a2;
    if (i == 0)      { a0 = A2[0][0]; a1 = A2[1][0]; a2 = A2[2][0]; }
    else if (i == 1) { a0 = A2[0][1]; a1 = A2[1][1]; a2 = A2[2][1]; }
    else             { a0 = A2[0][2]; a1 = A2[1][2]; a2 = A2[2][2]; }

    // Fused stage1+2: T2[j][o][p] = sum_n A[n][j] * (sum_m a_m C0[m][n][o][p])
    u64 T2[27];
#pragma unroll
    for (int o = 0; o < 3; o++) {
#pragma unroll
        for (int p = 0; p < 3; p++) {
            u64 t1[3];
#pragma unroll
            for (int n = 0; n < 3; n++) {
                t1[n] = f2fma(a0, c0s2[((0 * 3 + n) * 3 + o) * 3 + p],
                        f2fma(a1, c0s2[((1 * 3 + n) * 3 + o) * 3 + p],
                        f2mul(a2, c0s2[((2 * 3 + n) * 3 + o) * 3 + p])));
            }
#pragma unroll
            for (int j = 0; j < 3; j++) {
                T2[(j * 3 + o) * 3 + p] =
                    f2fma(A2[0][j], t1[0],
                    f2fma(A2[1][j], t1[1],
                    f2mul(A2[2][j], t1[2])));
            }
        }
    }

    // Fused stage3+4: per (j,k) build t3[p], emit 3 STG.64 immediately
    char* const outb = reinterpret_cast<char*>(out)
                     + ((size_t)(b * 81 + i * 27) * G3 + v) * sizeof(float);
#pragma unroll
    for (int j = 0; j < 3; j++) {
#pragma unroll
        for (int k = 0; k < 3; k++) {
            u64 t3[3];
#pragma unroll
            for (int p = 0; p < 3; p++) {
                t3[p] = f2fma(A2[0][k], T2[(j * 3 + 0) * 3 + p],
                        f2fma(A2[1][k], T2[(j * 3 + 1) * 3 + p],
                        f2mul(A2[2][k], T2[(j * 3 + 2) * 3 + p])));
            }
#pragma unroll
            for (int l = 0; l < 3; l++) {
                *reinterpret_cast<u64*>(
                    outb + (size_t)((j * 3 + k) * 3 + l) * G3 * sizeof(float)) =
                    f2fma(A2[0][l], t3[0],
                    f2fma(A2[1][l], t3[1],
                    f2mul(A2[2][l], t3[2])));
            }
        }
    }
}

extern "C" void kernel_launch(void* const* d_in, const int* in_sizes, int n_in,
                              void* d_out, int out_size)
{
    const float* alpha = (const float*)d_in[0];   // (B,3,3,G,G,G) float32
    const float* C0    = (const float*)d_in[1];   // (3,3,3,3) float32
    float* out         = (float*)d_out;           // (B,3,3,3,3,G,G,G) float32

    const int pairs_total = in_sizes[0] / 18;     // B * G^3 / 2
    const int threads = 128;
    dim3 grid((pairs_total + threads - 1) / threads, 3, 1);  // y = output index i
    alphaC0_kernel<<<grid, threads>>>(alpha, C0, out, pairs_total);
}

// round 8
// speedup vs baseline: 1.2736x; 1.2736x over previous
#include <cuda_runtime.h>

#define G3 (64 * 64 * 64)          // 262144 voxels per batch
#define PAIRS_PER_B (G3 / 2)       // 131072 voxel pairs per batch

typedef unsigned long long u64;

// C0 duplicated into both f32x2 lanes, resident in constant memory.
// Constant-port loads (LDC) bypass the L1tex/MIO path that STG saturates.
__constant__ u64 C0C2[81];
__device__ u64 c0_dup_scratch[81];

__device__ __forceinline__ u64 f2fma(u64 a, u64 b, u64 c) {
    u64 d; asm("fma.rn.f32x2 %0, %1, %2, %3;" : "=l"(d) : "l"(a), "l"(b), "l"(c)); return d;
}
__device__ __forceinline__ u64 f2mul(u64 a, u64 b) {
    u64 d; asm("mul.rn.f32x2 %0, %1, %2;" : "=l"(d) : "l"(a), "l"(b)); return d;
}

// Init: duplicate the 81 C0 floats into u64 {x,x} pairs in global scratch.
__global__ void dup_c0_kernel(const float* __restrict__ C0) {
    int t = threadIdx.x;
    if (t < 81) {
        float x = C0[t];
        u64 d; asm("mov.b64 %0, {%1, %1};" : "=l"(d) : "f"(x));
        c0_dup_scratch[t] = d;
    }
}

// One thread = one voxel PAIR (v, v+1), all 3 output indices i (rolled loop).
// Same skeleton as the 41.7us best; C0 moved smem->constant (removes 243
// LDS/thread from the MIO budget, whose STG+LDS load was the binding unit).
__global__ void __launch_bounds__(128, 4)
alphaC0_kernel(const float* __restrict__ alpha,
               float* __restrict__ out,
               int pairs_total)
{
    const int tid = blockIdx.x * blockDim.x + threadIdx.x;
    if (tid >= pairs_total) return;

    const int b = tid >> 17;                   // / PAIRS_PER_B
    const int v = (tid & (PAIRS_PER_B - 1)) * 2;

    // A2[m][c] = packed { A(v)[m][c], A(v+1)[m][c] }
    u64 A2[3][3];
#pragma unroll
    for (int m = 0; m < 3; m++)
#pragma unroll
        for (int c = 0; c < 3; c++)
            A2[m][c] = *reinterpret_cast<const u64*>(
                &alpha[(size_t)((b * 3 + m) * 3 + c) * G3 + v]);

    const char* outb0 = reinterpret_cast<const char*>(out)
                      + ((size_t)b * 81 * G3 + v) * sizeof(float);

#pragma unroll 1
    for (int i = 0; i < 3; i++) {
        u64 a0, a1, a2;
        if (i == 0)      { a0 = A2[0][0]; a1 = A2[1][0]; a2 = A2[2][0]; }
        else if (i == 1) { a0 = A2[0][1]; a1 = A2[1][1]; a2 = A2[2][1]; }
        else             { a0 = A2[0][2]; a1 = A2[1][2]; a2 = A2[2][2]; }

        // Fused stage1+2: T2[j][o][p] = sum_n A[n][j] * (sum_m a_m C0[m][n][o][p])
        u64 T2[27];
#pragma unroll
        for (int o = 0; o < 3; o++) {
#pragma unroll
            for (int p = 0; p < 3; p++) {
                u64 t1[3];
#pragma unroll
                for (int n = 0; n < 3; n++) {
                    t1[n] = f2fma(a0, C0C2[((0 * 3 + n) * 3 + o) * 3 + p],
                            f2fma(a1, C0C2[((1 * 3 + n) * 3 + o) * 3 + p],
                            f2mul(a2, C0C2[((2 * 3 + n) * 3 + o) * 3 + p])));
                }
#pragma unroll
                for (int j = 0; j < 3; j++) {
                    T2[(j * 3 + o) * 3 + p] =
                        f2fma(A2[0][j], t1[0],
                        f2fma(A2[1][j], t1[1],
                        f2mul(A2[2][j], t1[2])));
                }
            }
        }

        // Fused stage3+4: per (j,k) build t3[p], emit 3 STG.64 immediately
        const char* outb = outb0 + (size_t)(i * 27) * G3 * sizeof(float);
#pragma unroll
        for (int j = 0; j < 3; j++) {
#pragma unroll
            for (int k = 0; k < 3; k++) {
                u64 t3[3];
#pragma unroll
                for (int p = 0; p < 3; p++) {
                    t3[p] = f2fma(A2[0][k], T2[(j * 3 + 0) * 3 + p],
                            f2fma(A2[1][k], T2[(j * 3 + 1) * 3 + p],
                            f2mul(A2[2][k], T2[(j * 3 + 2) * 3 + p])));
                }
#pragma unroll
                for (int l = 0; l < 3; l++) {
                    *reinterpret_cast<u64*>(const_cast<char*>(
                        outb + (size_t)((j * 3 + k) * 3 + l) * G3 * sizeof(float))) =
                        f2fma(A2[0][l], t3[0],
                        f2fma(A2[1][l], t3[1],
                        f2mul(A2[2][l], t3[2])));
                }
            }
        }
    }
}

extern "C" void kernel_launch(void* const* d_in, const int* in_sizes, int n_in,
                              void* d_out, int out_size)
{
    const float* alpha = (const float*)d_in[0];   // (B,3,3,G,G,G) float32
    const float* C0    = (const float*)d_in[1];   // (3,3,3,3) float32
    float* out         = (float*)d_out;           // (B,3,3,3,3,G,G,G) float32

    // Stage C0 -> duplicated-pair scratch -> constant memory (all async,
    // graph-capturable: kernel node + D2D memcpy node + kernel node).
    dup_c0_kernel<<<1, 128>>>(C0);
    void* scratch_ptr = nullptr;
    cudaGetSymbolAddress(&scratch_ptr, c0_dup_scratch);
    cudaMemcpyToSymbolAsync(C0C2, scratch_ptr, 81 * sizeof(u64), 0,
                            cudaMemcpyDeviceToDevice);

    const int pairs_total = in_sizes[0] / 18;     // B * G^3 / 2
    const int threads = 128;
    const int blocks = (pairs_total + threads - 1) / threads;
    alphaC0_kernel<<<blocks, threads>>>(alpha, out, pairs_total);
}